// round 1
// baseline (speedup 1.0000x reference)
#include <cuda_runtime.h>
#include <cuda_bf16.h>
#include <math.h>

// Problem dims (fixed per reference)
#define B_  16
#define N_  1024
#define FIN 128
#define FO  64
#define ALPHA_ 0.2f

// Scratch (device globals: no allocation allowed)
__device__ float g_h[B_ * N_ * FO];           // 4 MB
__device__ float g_s1[B_ * N_], g_p1[B_ * N_], g_q1[B_ * N_];
__device__ float g_s2[B_ * N_], g_p2[B_ * N_], g_q2[B_ * N_];

// ---------------------------------------------------------------------------
// Kernel 1: h = inp @ W   (per block: 32 rows of one batch, all 64 outputs)
// ---------------------------------------------------------------------------
__global__ __launch_bounds__(256) void k_h_gemm(const float* __restrict__ inp,
                                                const float* __restrict__ W) {
    __shared__ float sW[FIN * FO];     // 32 KB
    __shared__ float sI[32 * FIN];     // 16 KB
    const int b = blockIdx.y;
    const int row0 = blockIdx.x * 32;
    const int t = threadIdx.x;

    for (int idx = t; idx < FIN * FO; idx += 256) sW[idx] = W[idx];
    const float4* ip = (const float4*)(inp + ((size_t)b * N_ + row0) * FIN);
    for (int idx = t; idx < 32 * FIN / 4; idx += 256) ((float4*)sI)[idx] = ip[idx];
    __syncthreads();

    const int o = t & 63;
    const int rg = t >> 6;             // 4 groups of 8 rows
    float acc[8];
#pragma unroll
    for (int r = 0; r < 8; r++) acc[r] = 0.f;

#pragma unroll 4
    for (int k = 0; k < FIN; k++) {
        const float wv = sW[k * FO + o];
#pragma unroll
        for (int r = 0; r < 8; r++)
            acc[r] += sI[(rg * 8 + r) * FIN + k] * wv;
    }
#pragma unroll
    for (int r = 0; r < 8; r++) {
        const int row = row0 + rg * 8 + r;
        g_h[((size_t)b * N_ + row) * FO + o] = acc[r];
    }
}

// ---------------------------------------------------------------------------
// Kernel 2: per-node scores s1 = h@a1, s2 = h@a2, and the 4 exps
// One warp per (b, n) row.
// ---------------------------------------------------------------------------
__global__ __launch_bounds__(256) void k_scores(const float* __restrict__ a) {
    const int warp = (blockIdx.x * 256 + threadIdx.x) >> 5;
    const int lane = threadIdx.x & 31;
    if (warp >= B_ * N_) return;

    const float* hrow = g_h + (size_t)warp * FO;
    const float h0 = hrow[lane];
    const float h1 = hrow[lane + 32];
    float s1 = h0 * a[lane]      + h1 * a[lane + 32];
    float s2 = h0 * a[64 + lane] + h1 * a[96 + lane];
#pragma unroll
    for (int off = 16; off > 0; off >>= 1) {
        s1 += __shfl_xor_sync(0xffffffffu, s1, off);
        s2 += __shfl_xor_sync(0xffffffffu, s2, off);
    }
    if (lane == 0) {
        g_s1[warp] = s1;
        g_p1[warp] = __expf(s1);
        g_q1[warp] = __expf(ALPHA_ * s1);
        g_s2[warp] = s2;
        g_p2[warp] = __expf(s2);
        g_q2[warp] = __expf(ALPHA_ * s2);
    }
}

// ---------------------------------------------------------------------------
// Kernel 3: fused  w_ij = mask * exp(lrelu(s1_i+s2_j)) ;  h' = (w @ h)/Z ; ELU
// Block: TI=64 rows x all 64 outputs of one batch. TJ=32 per step.
// Threads: 256 = 16 o-threads x 16 i-threads; each thread: 4i x 4o tile.
// ---------------------------------------------------------------------------
__global__ __launch_bounds__(256) void k_attn(const int* __restrict__ adj,
                                              float* __restrict__ out) {
    __shared__ float hs[32 * FO];        // 8 KB  : h tile  [j][o]
    __shared__ float ws[64 * 33];        // 8.25KB: weights [i][j], padded
    __shared__ float s1s[64], p1s[64], q1s[64];
    __shared__ float s2s[N_], p2s[N_], q2s[N_];   // 12 KB (full j range)

    const int b  = blockIdx.y;
    const int i0 = blockIdx.x * 64;
    const int t  = threadIdx.x;

    if (t < 64) {
        const int gi = b * N_ + i0 + t;
        s1s[t] = g_s1[gi]; p1s[t] = g_p1[gi]; q1s[t] = g_q1[gi];
    }
    for (int idx = t; idx < N_; idx += 256) {
        const int gj = b * N_ + idx;
        s2s[idx] = g_s2[gj]; p2s[idx] = g_p2[gj]; q2s[idx] = g_q2[gj];
    }

    const int ot = t & 15;       // o-thread: outputs 4*ot .. 4*ot+3
    const int it = t >> 4;       // i-thread: rows   4*it .. 4*it+3
    float acc[4][4];
    float z[4];
#pragma unroll
    for (int k = 0; k < 4; k++) {
        z[k] = 0.f;
#pragma unroll
        for (int c = 0; c < 4; c++) acc[k][c] = 0.f;
    }

    const int*   adjb = adj + (size_t)b * N_ * N_;
    const float* hb   = g_h + (size_t)b * N_ * FO;

    const int jt = t & 31;       // for w-compute phase
    const int ib = t >> 5;       // 0..7

    for (int j0 = 0; j0 < N_; j0 += 32) {
        __syncthreads();   // protects hs/ws from previous iteration reads; orders preload
        // load h tile [32 x 64]
#pragma unroll
        for (int k = 0; k < 8; k++) {
            const int idx = t + k * 256;
            hs[idx] = hb[j0 * FO + idx];
        }
        // compute weights for 64 x 32 tile
        const float s2v = s2s[j0 + jt];
        const float p2v = p2s[j0 + jt];
        const float q2v = q2s[j0 + jt];
#pragma unroll
        for (int k = 0; k < 8; k++) {
            const int il = ib * 8 + k;
            const int av = adjb[(size_t)(i0 + il) * N_ + j0 + jt];
            const float tt = s1s[il] + s2v;
            float w = 0.f;
            if (av > 0) w = (tt > 0.f) ? p1s[il] * p2v : q1s[il] * q2v;
            ws[il * 33 + jt] = w;
        }
        __syncthreads();
        // accumulate: 4i x 4o register tile
        const float4* hs4 = (const float4*)hs;
#pragma unroll 4
        for (int jj = 0; jj < 32; jj++) {
            const float4 hv = hs4[jj * 16 + ot];
#pragma unroll
            for (int k = 0; k < 4; k++) {
                const float wv = ws[(it * 4 + k) * 33 + jj];
                z[k]      += wv;
                acc[k][0] += wv * hv.x;
                acc[k][1] += wv * hv.y;
                acc[k][2] += wv * hv.z;
                acc[k][3] += wv * hv.w;
            }
        }
    }

    // normalize + ELU + store
#pragma unroll
    for (int k = 0; k < 4; k++) {
        const int i = i0 + it * 4 + k;
        const float inv = 1.f / z[k];
        float4 r;
        float v;
        v = acc[k][0] * inv; r.x = (v > 0.f) ? v : expm1f(v);
        v = acc[k][1] * inv; r.y = (v > 0.f) ? v : expm1f(v);
        v = acc[k][2] * inv; r.z = (v > 0.f) ? v : expm1f(v);
        v = acc[k][3] * inv; r.w = (v > 0.f) ? v : expm1f(v);
        ((float4*)out)[(((size_t)b * N_ + i) * FO >> 2) + ot] = r;
    }
}

// ---------------------------------------------------------------------------
extern "C" void kernel_launch(void* const* d_in, const int* in_sizes, int n_in,
                              void* d_out, int out_size) {
    const float* inp = (const float*)d_in[0];   // (16,1024,128) f32
    const int*   adj = (const int*)d_in[1];     // (16,1024,1024) i32
    const float* W   = (const float*)d_in[2];   // (128,64) f32
    const float* a   = (const float*)d_in[3];   // (128,1) f32
    float* out = (float*)d_out;                 // (16,1024,64) f32

    k_h_gemm<<<dim3(N_ / 32, B_), 256>>>(inp, W);
    k_scores<<<(B_ * N_ * 32 + 255) / 256, 256>>>(a);
    k_attn<<<dim3(N_ / 64, B_), 256>>>(adj, out);
}